// round 13
// baseline (speedup 1.0000x reference)
#include <cuda_runtime.h>
#include <cuda_fp16.h>
#include <math.h>
#include <stdint.h>

#define NN 50000
#define NE 800000

// ---------------- scratch ----------------------------------------------------
__device__ __align__(16) __half g_feat_h[NN * 256]; // GEMM output (fp16) for gathers
__device__ __align__(16) __half g_xh[NN * 256];     // presplit x hi; later h2 hi
__device__ __align__(16) __half g_xl[NN * 256];     // presplit x lo; later h2 lo
__device__ __align__(16) __half g_h1h[NN * 256];    // layer0 out hi
__device__ __align__(16) __half g_h1l[NN * 256];    // layer0 out lo
__device__ __align__(16) float  g_feat2[NN * 16];
__device__ __align__(16) float  g_res2[NN * 16];
__device__ __align__(16) __half2 g_w0h[128 * 256];  // W packed k-pairs (hi only)
__device__ __align__(16) __half2 g_w1h[128 * 256];
__device__ __align__(16) __half2 g_w2h[128 * 32];   // [W2|rW2] packed hi
__device__ __align__(16) __half2 g_w2l[128 * 32];   // [W2|rW2] packed lo
__device__ __align__(16) float g_el[NN * 4];
__device__ __align__(16) float g_er[NN * 4];
__device__ int g_deg[NN];
__device__ int g_rowptr[NN + 1];
__device__ int g_pos[NN];
__device__ int g_csr_src[NE];

// ---------------- CSR build --------------------------------------------------
__global__ void k_hist(const int* __restrict__ dst) {
    int e = blockIdx.x * blockDim.x + threadIdx.x;
    if (e < NE) atomicAdd(&g_deg[dst[e]], 1);
}

__global__ void k_scan() {
    __shared__ int warp_pref[32];
    const int T = 1024;
    int t = threadIdx.x;
    const int per = (NN + T - 1) / T;
    int begin = t * per;
    int end = min(begin + per, NN);
    if (begin > NN) begin = NN;
    if (end < begin) end = begin;

    int sum = 0;
    for (int i = begin; i < end; i++) sum += g_deg[i];

    int lane = t & 31, wid = t >> 5;
    int v = sum;
#pragma unroll
    for (int o = 1; o < 32; o <<= 1) {
        int u = __shfl_up_sync(0xffffffffu, v, o);
        if (lane >= o) v += u;
    }
    if (lane == 31) warp_pref[wid] = v;
    __syncthreads();
    if (wid == 0) {
        int w = warp_pref[lane];
#pragma unroll
        for (int o = 1; o < 32; o <<= 1) {
            int u = __shfl_up_sync(0xffffffffu, w, o);
            if (lane >= o) w += u;
        }
        warp_pref[lane] = w;
    }
    __syncthreads();
    int excl = v - sum + (wid ? warp_pref[wid - 1] : 0);

    int run = excl;
    for (int i = begin; i < end; i++) {
        g_rowptr[i] = run;
        g_pos[i] = run;
        run += g_deg[i];
    }
    if (t == T - 1) g_rowptr[NN] = run;
}

__global__ void k_scatter(const int* __restrict__ src, const int* __restrict__ dst) {
    int e = blockIdx.x * blockDim.x + threadIdx.x;
    if (e < NE) {
        int p = atomicAdd(&g_pos[dst[e]], 1);
        g_csr_src[p] = src[e];
    }
}

// ---------------- presplit helpers -------------------------------------------
__device__ __forceinline__ void split2(float x, float y, __half2& hi, __half2& lo) {
    __half hx = __float2half_rn(x), hy = __float2half_rn(y);
    hi = __halves2half2(hx, hy);
    lo = __floats2half2_rn(x - __half2float(hx), y - __half2float(hy));
}

__global__ void k_presplit(const float4* __restrict__ A, uint2* __restrict__ H,
                           uint2* __restrict__ L, int n4) {
    int i = blockIdx.x * blockDim.x + threadIdx.x;
    if (i >= n4) return;
    float4 v = A[i];
    __half2 h0, l0, h1, l1;
    split2(v.x, v.y, h0, l0);
    split2(v.z, v.w, h1, l1);
    H[i] = make_uint2(*(uint32_t*)&h0, *(uint32_t*)&h1);
    L[i] = make_uint2(*(uint32_t*)&l0, *(uint32_t*)&l1);
}

__global__ void k_presplitW(const float* __restrict__ W0, const float* __restrict__ W1,
                            __half2* __restrict__ P0, __half2* __restrict__ P1) {
    int idx = blockIdx.x * blockDim.x + threadIdx.x;
    if (idx >= 2 * 128 * 256) return;
    const float* W = (idx < 128 * 256) ? W0 : W1;
    __half2* P = (idx < 128 * 256) ? P0 : P1;
    int li = idx & (128 * 256 - 1);
    int kp = li >> 8, n = li & 255;
    float a = W[(2 * kp) * 256 + n];
    float b = W[(2 * kp + 1) * 256 + n];
    P[li] = __halves2half2(__float2half_rn(a), __float2half_rn(b));
}

__global__ void k_presplitW2(const float* __restrict__ W2, const float* __restrict__ rW2,
                             __half2* __restrict__ Ph, __half2* __restrict__ Pl) {
    int idx = blockIdx.x * blockDim.x + threadIdx.x;
    if (idx >= 128 * 32) return;
    int kp = idx >> 5, n = idx & 31;
    float a, b;
    if (n < 16) { a = W2[(2 * kp) * 16 + n];      b = W2[(2 * kp + 1) * 16 + n]; }
    else        { a = rW2[(2 * kp) * 16 + n - 16]; b = rW2[(2 * kp + 1) * 16 + n - 16]; }
    __half2 h, l;
    split2(a, b, h, l);
    Ph[idx] = h;
    Pl[idx] = l;
}

// ---------------- MMA / copy primitives --------------------------------------
__device__ __forceinline__ void mma16(float* d, const uint32_t* a, const uint32_t* b) {
    asm volatile(
        "mma.sync.aligned.m16n8k16.row.col.f32.f16.f16.f32 "
        "{%0,%1,%2,%3}, {%4,%5,%6,%7}, {%8,%9}, {%0,%1,%2,%3};\n"
        : "+f"(d[0]), "+f"(d[1]), "+f"(d[2]), "+f"(d[3])
        : "r"(a[0]), "r"(a[1]), "r"(a[2]), "r"(a[3]), "r"(b[0]), "r"(b[1]));
}

#define LDSM4(r0, r1, r2, r3, addr)                                           \
    asm volatile("ldmatrix.sync.aligned.m8n8.x4.shared.b16 {%0,%1,%2,%3}, [%4];" \
                 : "=r"(r0), "=r"(r1), "=r"(r2), "=r"(r3) : "r"(addr))

#define CP16(dst, src, n)                                                     \
    asm volatile("cp.async.cg.shared.global [%0], [%1], 16, %2;\n"            \
                 :: "r"(dst), "l"(src), "r"(n))
#define CPCOMMIT() asm volatile("cp.async.commit_group;\n" ::: "memory")
#define CPWAIT0()  asm volatile("cp.async.wait_group 0;\n" ::: "memory")

// ---------------- big GEMM: BK=32, XOR-swizzled A rows, 2-term ---------------
#define AG_ROWB 64
#define AG_STAGEB (128 * AG_ROWB)
#define BG_ROWB 288
#define BG_STAGEB (16 * BG_ROWB)

__global__ __launch_bounds__(256, 2) void k_gemm_tc(
    const __half* __restrict__ Axh, const __half* __restrict__ Axl,
    const __half2* __restrict__ Wph,
    __half* __restrict__ Ch, const float* __restrict__ pal,
    const float* __restrict__ pare, int M) {
    const int K = 256, N = 256;
    __shared__ __half2 Ah[2][128][16];
    __shared__ __half2 Al[2][128][16];
    __shared__ __half2 Bh[2][16][72];
    __shared__ float s_el[2][128];
    __shared__ float s_er[2][128];

    int tid = threadIdx.x;
    int lane = tid & 31;
    int wid = tid >> 5;
    int warp_n = wid & 1;
    int m_base = (wid >> 1) * 32;
    int n_base = warp_n * 32;
    int row0 = blockIdx.y * 128;
    int col0 = blockIdx.x * 64;
    int head = col0 >> 6;

    float acc[2][4][4];
#pragma unroll
    for (int mt = 0; mt < 2; mt++)
#pragma unroll
        for (int nt = 0; nt < 4; nt++)
#pragma unroll
            for (int i = 0; i < 4; i++) acc[mt][nt][i] = 0.f;

    int arow0 = tid >> 2, ac0 = tid & 3;
    int arow1 = (tid + 256) >> 2, ac1 = tid & 3;
    int gr0 = row0 + arow0, gr1 = row0 + arow1;
    int aok0 = (gr0 < M) ? 16 : 0, aok1 = (gr1 < M) ? 16 : 0;
    int grc0 = min(gr0, M - 1), grc1 = min(gr1, M - 1);
    uint32_t adst0 = arow0 * AG_ROWB + (ac0 ^ ((arow0 >> 1) & 3)) * 16;
    uint32_t adst1 = arow1 * AG_ROWB + (ac1 ^ ((arow1 >> 1) & 3)) * 16;
    int brow = tid >> 4, bchk = tid & 15;

    uint32_t ah_b = (uint32_t)__cvta_generic_to_shared(&Ah[0][0][0]);
    uint32_t al_b = (uint32_t)__cvta_generic_to_shared(&Al[0][0][0]);
    uint32_t bh_b = (uint32_t)__cvta_generic_to_shared(&Bh[0][0][0]);
    uint32_t b_dst = bh_b + brow * BG_ROWB + bchk * 16;

    int jq = lane >> 2;
    int jc = lane & 3;
    int lrow = (lane & 7) + ((lane >> 3) & 1) * 8;
    int lu = lane >> 4;

    auto stageA = [&](int st, int k0) {
        const __half* s0h = Axh + (size_t)grc0 * K + k0 + ac0 * 8;
        const __half* s0l = Axl + (size_t)grc0 * K + k0 + ac0 * 8;
        const __half* s1h = Axh + (size_t)grc1 * K + k0 + ac1 * 8;
        const __half* s1l = Axl + (size_t)grc1 * K + k0 + ac1 * 8;
        uint32_t so = st ? AG_STAGEB : 0;
        CP16(ah_b + so + adst0, s0h, aok0);
        CP16(al_b + so + adst0, s0l, aok0);
        CP16(ah_b + so + adst1, s1h, aok1);
        CP16(al_b + so + adst1, s1l, aok1);
    };
    auto stageB = [&](int st, int k0) {
        uint32_t so = st ? BG_STAGEB : 0;
        CP16(b_dst + so, Wph + ((size_t)(k0 >> 1) + brow) * N + col0 + bchk * 4, 16);
    };

    stageA(0, 0);
    stageB(0, 0);
    CPCOMMIT();

    const int NS = K / 32;
    for (int s = 0; s < NS; s++) {
        int cur = s & 1;
        CPWAIT0();
        __syncthreads();
        if (s + 1 < NS) {
            int k0 = (s + 1) * 32;
            stageA(cur ^ 1, k0);
            stageB(cur ^ 1, k0);
            CPCOMMIT();
        }

        uint32_t a_st = cur ? AG_STAGEB : 0;
#pragma unroll
        for (int sub = 0; sub < 2; sub++) {
            uint32_t ah[2][4], al_[2][4];
#pragma unroll
            for (int mt = 0; mt < 2; mt++) {
                int r = m_base + mt * 16 + lrow;
                uint32_t unit = (uint32_t)((lu + sub * 2) ^ ((r >> 1) & 3));
                uint32_t off = a_st + (uint32_t)r * AG_ROWB + unit * 16;
                LDSM4(ah[mt][0], ah[mt][1], ah[mt][2], ah[mt][3], ah_b + off);
                LDSM4(al_[mt][0], al_[mt][1], al_[mt][2], al_[mt][3], al_b + off);
            }
            uint32_t bh[4][2];
#pragma unroll
            for (int nt = 0; nt < 4; nt++) {
                int n = n_base + nt * 8 + jq;
                bh[nt][0] = *(const uint32_t*)&Bh[cur][sub * 8 + jc][n];
                bh[nt][1] = *(const uint32_t*)&Bh[cur][sub * 8 + jc + 4][n];
            }
#pragma unroll
            for (int mt = 0; mt < 2; mt++)
#pragma unroll
                for (int nt = 0; nt < 4; nt++) {
                    mma16(acc[mt][nt], ah[mt], bh[nt]);
                    mma16(acc[mt][nt], al_[mt], bh[nt]);
                }
        }
    }

    float elv[4] = {0.f, 0.f, 0.f, 0.f}, erv[4] = {0.f, 0.f, 0.f, 0.f};
#pragma unroll
    for (int mt = 0; mt < 2; mt++)
#pragma unroll
        for (int nt = 0; nt < 4; nt++) {
            int r = row0 + m_base + mt * 16 + jq;
            int cl = n_base + nt * 8 + 2 * jc;
            int c = col0 + cl;
            if (r < M)
                *(__half2*)&Ch[(size_t)r * N + c] =
                    __floats2half2_rn(acc[mt][nt][0], acc[mt][nt][1]);
            if (r + 8 < M)
                *(__half2*)&Ch[(size_t)(r + 8) * N + c] =
                    __floats2half2_rn(acc[mt][nt][2], acc[mt][nt][3]);
            float w0 = pal[c], w1 = pal[c + 1];
            float u0 = pare[c], u1 = pare[c + 1];
            elv[mt * 2]     += acc[mt][nt][0] * w0 + acc[mt][nt][1] * w1;
            elv[mt * 2 + 1] += acc[mt][nt][2] * w0 + acc[mt][nt][3] * w1;
            erv[mt * 2]     += acc[mt][nt][0] * u0 + acc[mt][nt][1] * u1;
            erv[mt * 2 + 1] += acc[mt][nt][2] * u0 + acc[mt][nt][3] * u1;
        }
#pragma unroll
    for (int o = 1; o <= 2; o <<= 1) {
#pragma unroll
        for (int i = 0; i < 4; i++) {
            elv[i] += __shfl_xor_sync(0xffffffffu, elv[i], o);
            erv[i] += __shfl_xor_sync(0xffffffffu, erv[i], o);
        }
    }
    if (jc == 0) {
#pragma unroll
        for (int i = 0; i < 4; i++) {
            int lr = m_base + (i >> 1) * 16 + (i & 1) * 8 + jq;
            s_el[warp_n][lr] = elv[i];
            s_er[warp_n][lr] = erv[i];
        }
    }
    __syncthreads();
    if (tid < 128) {
        int r = row0 + tid;
        if (r < M) {
            g_el[r * 4 + head] = s_el[0][tid] + s_el[1][tid];
            g_er[r * 4 + head] = s_er[0][tid] + s_er[1][tid];
        }
    }
}

// ---------------- layer-2 GEMM (BK=16 path, verified) ------------------------
#define A_ROWB 48
#define A_STAGEB (128 * A_ROWB)
#define B2_ROWB 160
#define B2_STAGEB (8 * B2_ROWB)

__global__ __launch_bounds__(256, 2) void k_gemm16_tc(
    const __half* __restrict__ Axh, const __half* __restrict__ Axl,
    const __half2* __restrict__ Wph, const __half2* __restrict__ Wpl,
    float* __restrict__ feat2, float* __restrict__ res2,
    const float* __restrict__ al2, const float* __restrict__ ar2, int M) {
    const int K = 256;
    __shared__ __half2 Ah[2][128][12];
    __shared__ __half2 Al[2][128][12];
    __shared__ __half2 Bh[2][8][40];
    __shared__ __half2 Bl[2][8][40];

    int tid = threadIdx.x;
    int lane = tid & 31;
    int wid = tid >> 5;
    int m_base = wid * 16;
    int row0 = blockIdx.x * 128;

    float acc[4][4];
#pragma unroll
    for (int nt = 0; nt < 4; nt++)
#pragma unroll
        for (int i = 0; i < 4; i++) acc[nt][i] = 0.f;

    int ar = tid >> 1;
    int acq = (tid & 1);
    int gr = row0 + ar;
    int aok = (gr < M) ? 16 : 0;
    int grc = min(gr, M - 1);
    int t2 = tid & 63;
    int kp = t2 >> 3;
    int chk = t2 & 7;
    bool isB = tid < 128;
    bool isHi = tid < 64;

    uint32_t ah_b = (uint32_t)__cvta_generic_to_shared(&Ah[0][0][0]);
    uint32_t al_b = (uint32_t)__cvta_generic_to_shared(&Al[0][0][0]);
    uint32_t bh_b = (uint32_t)__cvta_generic_to_shared(&Bh[0][0][0]);
    uint32_t bl_b = (uint32_t)__cvta_generic_to_shared(&Bl[0][0][0]);
    uint32_t a_dst = ar * A_ROWB + acq * 16;
    uint32_t b_dst = (isHi ? bh_b : bl_b) + kp * B2_ROWB + chk * 16;
    const __half2* Wsrc = isHi ? Wph : Wpl;

    uint32_t lm_off = (uint32_t)(m_base + (lane & 7) + ((lane >> 3) & 1) * 8) * A_ROWB
                      + (lane >> 4) * 16;

    int jq = lane >> 2;
    int jc = lane & 3;

    {
        const __half* sa = Axh + (size_t)grc * K + acq * 8;
        const __half* sl = Axl + (size_t)grc * K + acq * 8;
        CP16(ah_b + a_dst, sa, aok);
        CP16(al_b + a_dst, sl, aok);
        if (isB) CP16(b_dst, Wsrc + (size_t)kp * 32 + chk * 4, 16);
        CPCOMMIT();
    }

    const int NS = K / 16;
    for (int s = 0; s < NS; s++) {
        int cur = s & 1;
        CPWAIT0();
        __syncthreads();
        if (s + 1 < NS) {
            int k0 = (s + 1) * 16;
            uint32_t stoff = (cur ^ 1) ? A_STAGEB : 0;
            const __half* sa = Axh + (size_t)grc * K + k0 + acq * 8;
            const __half* sl = Axl + (size_t)grc * K + k0 + acq * 8;
            CP16(ah_b + stoff + a_dst, sa, aok);
            CP16(al_b + stoff + a_dst, sl, aok);
            uint32_t bst = (cur ^ 1) ? B2_STAGEB : 0;
            if (isB) CP16(b_dst + bst, Wsrc + ((size_t)(k0 >> 1) + kp) * 32 + chk * 4, 16);
            CPCOMMIT();
        }

        uint32_t ah[4], al_[4];
        uint32_t a_st = cur ? A_STAGEB : 0;
        LDSM4(ah[0], ah[1], ah[2], ah[3], ah_b + a_st + lm_off);
        LDSM4(al_[0], al_[1], al_[2], al_[3], al_b + a_st + lm_off);
        uint32_t bh[4][2], bl[4][2];
#pragma unroll
        for (int nt = 0; nt < 4; nt++) {
            int n = nt * 8 + jq;
            bh[nt][0] = *(const uint32_t*)&Bh[cur][jc][n];
            bh[nt][1] = *(const uint32_t*)&Bh[cur][jc + 4][n];
            bl[nt][0] = *(const uint32_t*)&Bl[cur][jc][n];
            bl[nt][1] = *(const uint32_t*)&Bl[cur][jc + 4][n];
        }
#pragma unroll
        for (int nt = 0; nt < 4; nt++) {
            mma16(acc[nt], ah, bh[nt]);
            mma16(acc[nt], al_, bh[nt]);
            mma16(acc[nt], ah, bl[nt]);
        }
    }

    int r0 = row0 + m_base + jq;
    int r1 = r0 + 8;
    float elv0 = 0.f, elv1 = 0.f, erv0 = 0.f, erv1 = 0.f;
#pragma unroll
    for (int nt = 0; nt < 4; nt++) {
        int c = nt * 8 + 2 * jc;
        if (nt < 2) {
            if (r0 < M) *(float2*)&feat2[(size_t)r0 * 16 + c] = make_float2(acc[nt][0], acc[nt][1]);
            if (r1 < M) *(float2*)&feat2[(size_t)r1 * 16 + c] = make_float2(acc[nt][2], acc[nt][3]);
            float w0 = al2[c], w1 = al2[c + 1];
            float u0 = ar2[c], u1 = ar2[c + 1];
            elv0 += acc[nt][0] * w0 + acc[nt][1] * w1;
            elv1 += acc[nt][2] * w0 + acc[nt][3] * w1;
            erv0 += acc[nt][0] * u0 + acc[nt][1] * u1;
            erv1 += acc[nt][2] * u0 + acc[nt][3] * u1;
        } else {
            int cc = c - 16;
            if (r0 < M) *(float2*)&res2[(size_t)r0 * 16 + cc] = make_float2(acc[nt][0], acc[nt][1]);
            if (r1 < M) *(float2*)&res2[(size_t)r1 * 16 + cc] = make_float2(acc[nt][2], acc[nt][3]);
        }
    }
#pragma unroll
    for (int o = 1; o <= 2; o <<= 1) {
        elv0 += __shfl_xor_sync(0xffffffffu, elv0, o);
        elv1 += __shfl_xor_sync(0xffffffffu, elv1, o);
        erv0 += __shfl_xor_sync(0xffffffffu, erv0, o);
        erv1 += __shfl_xor_sync(0xffffffffu, erv1, o);
    }
    if (jc == 0) {
        if (r0 < M) { g_el[r0] = elv0; g_er[r0] = erv0; }
        if (r1 < M) { g_el[r1] = elv1; g_er[r1] = erv1; }
    }
}

// ---------------- fused softmax-aggregate ------------------------------------
__device__ __forceinline__ float mishf(float x) {
    float sp = fmaxf(x, 0.f) + log1pf(__expf(-fabsf(x)));
    return x * tanhf(sp);
}

__device__ __forceinline__ float lrelu(float e) { return (e > 0.f) ? e : 0.2f * e; }

// lane l owns output columns [8l, 8l+8). 4 edges in flight per iteration.
template <int MODE>
__global__ __launch_bounds__(256) void k_agg4(
    const __half* __restrict__ feath, const float* __restrict__ resf,
    const __half* __restrict__ resh, const __half* __restrict__ resl,
    const float* __restrict__ bias,
    __half* __restrict__ outh, __half* __restrict__ outl) {
    __shared__ float4 sw[8][32];
    int node = (blockIdx.x * blockDim.x + threadIdx.x) >> 5;
    int lane = threadIdx.x & 31;
    int warp = (threadIdx.x >> 5);
    if (node >= NN) return;
    int start = g_rowptr[node], end = g_rowptr[node + 1];
    float4 er4 = *(const float4*)&g_er[node * 4];
    int h = lane >> 3;
    float acc[8] = {0.f, 0.f, 0.f, 0.f, 0.f, 0.f, 0.f, 0.f};
    float ss0 = 0.f, ss1 = 0.f, ss2 = 0.f, ss3 = 0.f;

    for (int base = start; base < end; base += 32) {
        int i = base + lane;
        int s = 0;
        float w0 = 0.f, w1 = 0.f, w2 = 0.f, w3 = 0.f;
        if (i < end) {
            s = g_csr_src[i];
            float4 el4 = *(const float4*)&g_el[s * 4];
            w0 = __expf(lrelu(el4.x + er4.x));
            w1 = __expf(lrelu(el4.y + er4.y));
            w2 = __expf(lrelu(el4.z + er4.z));
            w3 = __expf(lrelu(el4.w + er4.w));
            ss0 += w0; ss1 += w1; ss2 += w2; ss3 += w3;
        }
        __syncwarp();
        sw[warp][lane] = make_float4(w0, w1, w2, w3);
        __syncwarp();
        int cnt = min(32, end - base);
        const float* swp = (const float*)&sw[warp][0];
        int j = 0;
        for (; j + 3 < cnt; j += 4) {
            int sj[4];
            float wq[4];
            uint4 v[4];
#pragma unroll
            for (int q = 0; q < 4; q++) {
                sj[q] = __shfl_sync(0xffffffffu, s, j + q);
                wq[q] = swp[(j + q) * 4 + h];
            }
#pragma unroll
            for (int q = 0; q < 4; q++)
                v[q] = *(const uint4*)(feath + (size_t)sj[q] * 256 + lane * 8);
#pragma unroll
            for (int q = 0; q < 4; q++) {
                float2 f0 = __half22float2(*(__half2*)&v[q].x);
                float2 f1 = __half22float2(*(__half2*)&v[q].y);
                float2 f2 = __half22float2(*(__half2*)&v[q].z);
                float2 f3 = __half22float2(*(__half2*)&v[q].w);
                acc[0] += wq[q] * f0.x; acc[1] += wq[q] * f0.y;
                acc[2] += wq[q] * f1.x; acc[3] += wq[q] * f1.y;
                acc[4] += wq[q] * f2.x; acc[5] += wq[q] * f2.y;
                acc[6] += wq[q] * f3.x; acc[7] += wq[q] * f3.y;
            }
        }
        for (; j < cnt; j++) {
            int sj = __shfl_sync(0xffffffffu, s, j);
            uint4 v = *(const uint4*)(feath + (size_t)sj * 256 + lane * 8);
            float w = swp[j * 4 + h];
            float2 f0 = __half22float2(*(__half2*)&v.x);
            float2 f1 = __half22float2(*(__half2*)&v.y);
            float2 f2 = __half22float2(*(__half2*)&v.z);
            float2 f3 = __half22float2(*(__half2*)&v.w);
            acc[0] += w * f0.x; acc[1] += w * f0.y;
            acc[2] += w * f1.x; acc[3] += w * f1.y;
            acc[4] += w * f2.x; acc[5] += w * f2.y;
            acc[6] += w * f3.x; acc[7] += w * f3.y;
        }
    }
#pragma unroll
    for (int o = 16; o; o >>= 1) {
        ss0 += __shfl_xor_sync(0xffffffffu, ss0, o);
        ss1 += __shfl_xor_sync(0xffffffffu, ss1, o);
        ss2 += __shfl_xor_sync(0xffffffffu, ss2, o);
        ss3 += __shfl_xor_sync(0xffffffffu, ss3, o);
    }
    bool has = (end > start);
    float inv;
    {
        float sssel = (h == 0) ? ss0 : (h == 1) ? ss1 : (h == 2) ? ss2 : ss3;
        inv = has ? 1.f / sssel : 0.f;
    }

    size_t off = (size_t)node * 256 + lane * 8;
    int bc = lane * 8;
    float o[8];
    if (MODE == 0) {
        float4 r0 = *(const float4*)&resf[off];
        float4 r1 = *(const float4*)&resf[off + 4];
        o[0] = acc[0] * inv + r0.x + bias[bc];
        o[1] = acc[1] * inv + r0.y + bias[bc + 1];
        o[2] = acc[2] * inv + r0.z + bias[bc + 2];
        o[3] = acc[3] * inv + r0.w + bias[bc + 3];
        o[4] = acc[4] * inv + r1.x + bias[bc + 4];
        o[5] = acc[5] * inv + r1.y + bias[bc + 5];
        o[6] = acc[6] * inv + r1.z + bias[bc + 6];
        o[7] = acc[7] * inv + r1.w + bias[bc + 7];
    } else {
        uint4 vh = *(const uint4*)(resh + off);
        uint4 vl = *(const uint4*)(resl + off);
        float2 rh[4], rl[4];
        rh[0] = __half22float2(*(__half2*)&vh.x); rl[0] = __half22float2(*(__half2*)&vl.x);
        rh[1] = __half22float2(*(__half2*)&vh.y); rl[1] = __half22float2(*(__half2*)&vl.y);
        rh[2] = __half22float2(*(__half2*)&vh.z); rl[2] = __half22float2(*(__half2*)&vl.z);
        rh[3] = __half22float2(*(__half2*)&vh.w); rl[3] = __half22float2(*(__half2*)&vl.w);
#pragma unroll
        for (int q = 0; q < 4; q++) {
            o[2 * q]     = acc[2 * q] * inv + rh[q].x + rl[q].x + bias[bc + 2 * q];
            o[2 * q + 1] = acc[2 * q + 1] * inv + rh[q].y + rl[q].y + bias[bc + 2 * q + 1];
        }
    }
#pragma unroll
    for (int q = 0; q < 8; q++) o[q] = mishf(o[q]);
    uint4 vh, vl;
    __half2 hh, ll;
    split2(o[0], o[1], hh, ll); vh.x = *(uint32_t*)&hh; vl.x = *(uint32_t*)&ll;
    split2(o[2], o[3], hh, ll); vh.y = *(uint32_t*)&hh; vl.y = *(uint32_t*)&ll;
    split2(o[4], o[5], hh, ll); vh.z = *(uint32_t*)&hh; vl.z = *(uint32_t*)&ll;
    split2(o[6], o[7], hh, ll); vh.w = *(uint32_t*)&hh; vl.w = *(uint32_t*)&ll;
    *(uint4*)(outh + off) = vh;
    *(uint4*)(outl + off) = vl;
}

// ---------------- softmax-aggregate layer2: quarter-warp, 4 edges/iter -------
__global__ __launch_bounds__(256) void k_agg2(
    const float* __restrict__ feat, const float* __restrict__ res,
    const float* __restrict__ bias, float* __restrict__ out) {
    int node = (blockIdx.x * blockDim.x + threadIdx.x) >> 5;
    int lane = threadIdx.x & 31;
    if (node >= NN) return;
    int start = g_rowptr[node], end = g_rowptr[node + 1];
    float er_n = g_er[node];
    int q = lane >> 3;      // quarter 0..3
    int sub = lane & 7;     // float2 slot (cols 2*sub, 2*sub+1)

    float2 acc = {0.f, 0.f};
    float ss = 0.f;
    for (int base = start; base < end; base += 32) {
        int i = base + lane;
        int s = 0;
        float w = 0.f;
        if (i < end) {
            s = g_csr_src[i];
            w = __expf(lrelu(g_el[s] + er_n));
            ss += w;
        }
        int cnt = min(32, end - base);
        for (int j = 0; j < cnt; j += 4) {
            if (j + q < cnt) {
                int   sj = __shfl_sync(0xffffffffu, s, j + q);
                float bw = __shfl_sync(0xffffffffu, w, j + q);
                float2 f = *(const float2*)&feat[(size_t)sj * 16 + 2 * sub];
                acc.x += bw * f.x;
                acc.y += bw * f.y;
            } else {
                __shfl_sync(0xffffffffu, s, j);   // keep warp converged
                __shfl_sync(0xffffffffu, w, j);
            }
        }
    }
#pragma unroll
    for (int o = 16; o; o >>= 1) ss += __shfl_xor_sync(0xffffffffu, ss, o);
    acc.x += __shfl_xor_sync(0xffffffffu, acc.x, 8);
    acc.y += __shfl_xor_sync(0xffffffffu, acc.y, 8);
    acc.x += __shfl_xor_sync(0xffffffffu, acc.x, 16);
    acc.y += __shfl_xor_sync(0xffffffffu, acc.y, 16);
    float inv = (end > start) ? 1.f / ss : 0.f;
    if (lane < 8) {
        float2 r = *(const float2*)&res[(size_t)node * 16 + 2 * sub];
        float2 b = *(const float2*)&bias[2 * sub];
        *(float2*)&out[(size_t)node * 16 + 2 * sub] =
            make_float2(acc.x * inv + r.x + b.x, acc.y * inv + r.y + b.y);
    }
}

// ---------------- launch -----------------------------------------------------
extern "C" void kernel_launch(void* const* d_in, const int* in_sizes, int n_in,
                              void* d_out, int out_size) {
    const float* x    = (const float*)d_in[0];
    const int*   src  = (const int*)d_in[1];
    const int*   dst  = (const int*)d_in[2];
    const float* W0   = (const float*)d_in[3];
    const float* al0  = (const float*)d_in[4];
    const float* ar0  = (const float*)d_in[5];
    const float* b0   = (const float*)d_in[6];
    const float* W1   = (const float*)d_in[7];
    const float* al1  = (const float*)d_in[8];
    const float* ar1  = (const float*)d_in[9];
    const float* b1   = (const float*)d_in[10];
    const float* W2   = (const float*)d_in[11];
    const float* al2  = (const float*)d_in[12];
    const float* ar2  = (const float*)d_in[13];
    const float* b2   = (const float*)d_in[14];
    const float* rW2  = (const float*)d_in[15];
    float* out = (float*)d_out;

    __half *feath, *xh, *xl, *h1h, *h1l;
    float *feat2, *res2;
    __half2 *w0h, *w1h, *w2h, *w2l;
    void* degp;
    cudaGetSymbolAddress((void**)&feath, g_feat_h);
    cudaGetSymbolAddress((void**)&xh, g_xh);
    cudaGetSymbolAddress((void**)&xl, g_xl);
    cudaGetSymbolAddress((void**)&h1h, g_h1h);
    cudaGetSymbolAddress((void**)&h1l, g_h1l);
    cudaGetSymbolAddress((void**)&feat2, g_feat2);
    cudaGetSymbolAddress((void**)&res2, g_res2);
    cudaGetSymbolAddress((void**)&w0h, g_w0h);
    cudaGetSymbolAddress((void**)&w1h, g_w1h);
    cudaGetSymbolAddress((void**)&w2h, g_w2h);
    cudaGetSymbolAddress((void**)&w2l, g_w2l);
    cudaGetSymbolAddress(&degp, g_deg);

    // fork a side stream for the CSR build
    cudaStream_t s2 = 0;
    cudaEvent_t evF = 0, evJ = 0;
    bool forked = (cudaStreamCreateWithFlags(&s2, cudaStreamNonBlocking) == cudaSuccess) &&
                  (cudaEventCreateWithFlags(&evF, cudaEventDisableTiming) == cudaSuccess) &&
                  (cudaEventCreateWithFlags(&evJ, cudaEventDisableTiming) == cudaSuccess);
    cudaStream_t sc = forked ? s2 : 0;

    if (forked) {
        cudaEventRecord(evF, 0);
        cudaStreamWaitEvent(s2, evF, 0);
    }
    cudaMemsetAsync(degp, 0, NN * sizeof(int), sc);
    k_hist<<<(NE + 255) / 256, 256, 0, sc>>>(dst);
    k_scan<<<1, 1024, 0, sc>>>();
    k_scatter<<<(NE + 255) / 256, 256, 0, sc>>>(src, dst);
    if (forked) cudaEventRecord(evJ, s2);

    // main stream: presplit + layer0 GEMM
    k_presplitW<<<(2 * 128 * 256 + 255) / 256, 256>>>(W0, W1, w0h, w1h);
    k_presplitW2<<<(128 * 32 + 255) / 256, 256>>>(W2, rW2, w2h, w2l);
    k_presplit<<<(NN * 64 + 255) / 256, 256>>>((const float4*)x, (uint2*)xh, (uint2*)xl, NN * 64);

    dim3 gtc(4, (NN + 127) / 128);
    int aggBlocks = (NN * 32 + 255) / 256;

    k_gemm_tc<<<gtc, 256>>>(xh, xl, w0h, feath, al0, ar0, NN);

    if (forked) cudaStreamWaitEvent(0, evJ, 0);

    k_agg4<0><<<aggBlocks, 256>>>(feath, x, nullptr, nullptr, b0, h1h, h1l);

    k_gemm_tc<<<gtc, 256>>>(h1h, h1l, w1h, feath, al1, ar1, NN);
    k_agg4<1><<<aggBlocks, 256>>>(feath, nullptr, h1h, h1l, b1, xh, xl);

    k_gemm16_tc<<<(NN + 127) / 128, 256>>>(xh, xl, w2h, w2l, feat2, res2, al2, ar2, NN);
    k_agg2<<<aggBlocks, 256>>>(feat2, res2, b2, out);
}

// round 14
// speedup vs baseline: 1.0448x; 1.0448x over previous
#include <cuda_runtime.h>
#include <cuda_fp16.h>
#include <math.h>
#include <stdint.h>

#define NN 50000
#define NE 800000

// ---------------- scratch ----------------------------------------------------
__device__ __align__(16) __half g_feat_h[NN * 256]; // GEMM output (fp16) for gathers
__device__ __align__(16) __half g_xh[NN * 256];     // presplit x hi; later h2 hi
__device__ __align__(16) __half g_xl[NN * 256];     // presplit x lo; later h2 lo
__device__ __align__(16) __half g_h1h[NN * 256];    // layer0 out hi
__device__ __align__(16) __half g_h1l[NN * 256];    // layer0 out lo
__device__ __align__(16) float  g_feat2[NN * 16];
__device__ __align__(16) float  g_res2[NN * 16];
__device__ __align__(16) __half2 g_w0h[128 * 256];  // W packed k-pairs (hi only)
__device__ __align__(16) __half2 g_w1h[128 * 256];
__device__ __align__(16) __half2 g_w2h[128 * 32];   // [W2|rW2] packed hi
__device__ __align__(16) __half2 g_w2l[128 * 32];   // [W2|rW2] packed lo
__device__ __align__(16) float g_el[NN * 4];
__device__ __align__(16) float g_er[NN * 4];
__device__ int g_deg[NN];
__device__ int g_rowptr[NN + 1];
__device__ int g_pos[NN];
__device__ int g_csr_src[NE];

// ---------------- CSR build --------------------------------------------------
__global__ void k_hist(const int* __restrict__ dst) {
    int e = blockIdx.x * blockDim.x + threadIdx.x;
    if (e < NE) atomicAdd(&g_deg[dst[e]], 1);
}

__global__ void k_scan() {
    __shared__ int warp_pref[32];
    const int T = 1024;
    int t = threadIdx.x;
    const int per = (NN + T - 1) / T;
    int begin = t * per;
    int end = min(begin + per, NN);
    if (begin > NN) begin = NN;
    if (end < begin) end = begin;

    int sum = 0;
    for (int i = begin; i < end; i++) sum += g_deg[i];

    int lane = t & 31, wid = t >> 5;
    int v = sum;
#pragma unroll
    for (int o = 1; o < 32; o <<= 1) {
        int u = __shfl_up_sync(0xffffffffu, v, o);
        if (lane >= o) v += u;
    }
    if (lane == 31) warp_pref[wid] = v;
    __syncthreads();
    if (wid == 0) {
        int w = warp_pref[lane];
#pragma unroll
        for (int o = 1; o < 32; o <<= 1) {
            int u = __shfl_up_sync(0xffffffffu, w, o);
            if (lane >= o) w += u;
        }
        warp_pref[lane] = w;
    }
    __syncthreads();
    int excl = v - sum + (wid ? warp_pref[wid - 1] : 0);

    int run = excl;
    for (int i = begin; i < end; i++) {
        g_rowptr[i] = run;
        g_pos[i] = run;
        run += g_deg[i];
    }
    if (t == T - 1) g_rowptr[NN] = run;
}

__global__ void k_scatter(const int* __restrict__ src, const int* __restrict__ dst) {
    int e = blockIdx.x * blockDim.x + threadIdx.x;
    if (e < NE) {
        int p = atomicAdd(&g_pos[dst[e]], 1);
        g_csr_src[p] = src[e];
    }
}

// ---------------- presplit helpers -------------------------------------------
__device__ __forceinline__ void split2(float x, float y, __half2& hi, __half2& lo) {
    __half hx = __float2half_rn(x), hy = __float2half_rn(y);
    hi = __halves2half2(hx, hy);
    lo = __floats2half2_rn(x - __half2float(hx), y - __half2float(hy));
}

__global__ void k_presplit(const float4* __restrict__ A, uint2* __restrict__ H,
                           uint2* __restrict__ L, int n4) {
    int i = blockIdx.x * blockDim.x + threadIdx.x;
    if (i >= n4) return;
    float4 v = A[i];
    __half2 h0, l0, h1, l1;
    split2(v.x, v.y, h0, l0);
    split2(v.z, v.w, h1, l1);
    H[i] = make_uint2(*(uint32_t*)&h0, *(uint32_t*)&h1);
    L[i] = make_uint2(*(uint32_t*)&l0, *(uint32_t*)&l1);
}

__global__ void k_presplitW(const float* __restrict__ W0, const float* __restrict__ W1,
                            __half2* __restrict__ P0, __half2* __restrict__ P1) {
    int idx = blockIdx.x * blockDim.x + threadIdx.x;
    if (idx >= 2 * 128 * 256) return;
    const float* W = (idx < 128 * 256) ? W0 : W1;
    __half2* P = (idx < 128 * 256) ? P0 : P1;
    int li = idx & (128 * 256 - 1);
    int kp = li >> 8, n = li & 255;
    float a = W[(2 * kp) * 256 + n];
    float b = W[(2 * kp + 1) * 256 + n];
    P[li] = __halves2half2(__float2half_rn(a), __float2half_rn(b));
}

__global__ void k_presplitW2(const float* __restrict__ W2, const float* __restrict__ rW2,
                             __half2* __restrict__ Ph, __half2* __restrict__ Pl) {
    int idx = blockIdx.x * blockDim.x + threadIdx.x;
    if (idx >= 128 * 32) return;
    int kp = idx >> 5, n = idx & 31;
    float a, b;
    if (n < 16) { a = W2[(2 * kp) * 16 + n];      b = W2[(2 * kp + 1) * 16 + n]; }
    else        { a = rW2[(2 * kp) * 16 + n - 16]; b = rW2[(2 * kp + 1) * 16 + n - 16]; }
    __half2 h, l;
    split2(a, b, h, l);
    Ph[idx] = h;
    Pl[idx] = l;
}

// ---------------- MMA / copy primitives --------------------------------------
__device__ __forceinline__ void mma16(float* d, const uint32_t* a, const uint32_t* b) {
    asm volatile(
        "mma.sync.aligned.m16n8k16.row.col.f32.f16.f16.f32 "
        "{%0,%1,%2,%3}, {%4,%5,%6,%7}, {%8,%9}, {%0,%1,%2,%3};\n"
        : "+f"(d[0]), "+f"(d[1]), "+f"(d[2]), "+f"(d[3])
        : "r"(a[0]), "r"(a[1]), "r"(a[2]), "r"(a[3]), "r"(b[0]), "r"(b[1]));
}

#define LDSM4(r0, r1, r2, r3, addr)                                           \
    asm volatile("ldmatrix.sync.aligned.m8n8.x4.shared.b16 {%0,%1,%2,%3}, [%4];" \
                 : "=r"(r0), "=r"(r1), "=r"(r2), "=r"(r3) : "r"(addr))

#define CP16(dst, src, n)                                                     \
    asm volatile("cp.async.cg.shared.global [%0], [%1], 16, %2;\n"            \
                 :: "r"(dst), "l"(src), "r"(n))
#define CPCOMMIT() asm volatile("cp.async.commit_group;\n" ::: "memory")
#define CPWAIT0()  asm volatile("cp.async.wait_group 0;\n" ::: "memory")

// ---------------- big GEMM: BM=128 BN=128 BK=32, 2-term, dynamic smem --------
// smem layout: Ah[2][128][64B] @0 (16KB), Al @16KB, B[2][2][16][72 half2] @32KB
#define AG_ROWB 64
#define AG_STAGEB (128 * AG_ROWB)      // 8192 per stage
#define BG_WSTR (16 * 288)             // 4608 bytes per warp_n region
#define BG_STAGEB (2 * BG_WSTR)        // 9216 per stage
#define GEMM_SMEM (16384 + 16384 + 2 * BG_STAGEB)   // 51200

__global__ __launch_bounds__(256, 2) void k_gemm_tc(
    const __half* __restrict__ Axh, const __half* __restrict__ Axl,
    const __half2* __restrict__ Wph,
    __half* __restrict__ Ch, const float* __restrict__ pal,
    const float* __restrict__ pare, int M) {
    const int K = 256, N = 256;
    extern __shared__ char dynsmem[];
    __half2* Bgen = (__half2*)(dynsmem + 32768);   // [2][2][16][72]

    int tid = threadIdx.x;
    int lane = tid & 31;
    int wid = tid >> 5;
    int warp_n = wid & 1;
    int m_base = (wid >> 1) * 32;
    int row0 = blockIdx.y * 128;
    int col0 = blockIdx.x * 128;
    int colw = col0 + warp_n * 64;
    int head = colw >> 6;

    float acc[2][8][4];
#pragma unroll
    for (int mt = 0; mt < 2; mt++)
#pragma unroll
        for (int nt = 0; nt < 8; nt++)
#pragma unroll
            for (int i = 0; i < 4; i++) acc[mt][nt][i] = 0.f;

    // A staging (identical to verified R12: XOR chunk swizzle)
    int arow0 = tid >> 2, ac0 = tid & 3;
    int arow1 = (tid + 256) >> 2, ac1 = tid & 3;
    int gr0 = row0 + arow0, gr1 = row0 + arow1;
    int aok0 = (gr0 < M) ? 16 : 0, aok1 = (gr1 < M) ? 16 : 0;
    int grc0 = min(gr0, M - 1), grc1 = min(gr1, M - 1);
    uint32_t adst0 = arow0 * AG_ROWB + (ac0 ^ ((arow0 >> 1) & 3)) * 16;
    uint32_t adst1 = arow1 * AG_ROWB + (ac1 ^ ((arow1 >> 1) & 3)) * 16;
    // B staging: thread t stages 16B chunk (brow, bchk) for BOTH warp_n halves
    int brow = tid >> 4, bchk = tid & 15;

    uint32_t sm_b = (uint32_t)__cvta_generic_to_shared(dynsmem);
    uint32_t ah_b = sm_b;
    uint32_t al_b = sm_b + 16384;
    uint32_t bh_b = sm_b + 32768;
    uint32_t b_dst0 = bh_b + brow * 288 + bchk * 16;
    uint32_t b_dst1 = b_dst0 + BG_WSTR;

    int jq = lane >> 2;
    int jc = lane & 3;
    int lrow = (lane & 7) + ((lane >> 3) & 1) * 8;
    int lu = lane >> 4;

    auto stageA = [&](int st, int k0) {
        const __half* s0h = Axh + (size_t)grc0 * K + k0 + ac0 * 8;
        const __half* s0l = Axl + (size_t)grc0 * K + k0 + ac0 * 8;
        const __half* s1h = Axh + (size_t)grc1 * K + k0 + ac1 * 8;
        const __half* s1l = Axl + (size_t)grc1 * K + k0 + ac1 * 8;
        uint32_t so = st ? AG_STAGEB : 0;
        CP16(ah_b + so + adst0, s0h, aok0);
        CP16(al_b + so + adst0, s0l, aok0);
        CP16(ah_b + so + adst1, s1h, aok1);
        CP16(al_b + so + adst1, s1l, aok1);
    };
    auto stageB = [&](int st, int k0) {
        uint32_t so = st ? BG_STAGEB : 0;
        const __half2* src = Wph + ((size_t)(k0 >> 1) + brow) * N + col0 + bchk * 4;
        CP16(b_dst0 + so, src, 16);
        CP16(b_dst1 + so, src + 64, 16);
    };

    stageA(0, 0);
    stageB(0, 0);
    CPCOMMIT();

    const int NS = K / 32;   // 8
    for (int s = 0; s < NS; s++) {
        int cur = s & 1;
        CPWAIT0();
        __syncthreads();
        if (s + 1 < NS) {
            int k0 = (s + 1) * 32;
            stageA(cur ^ 1, k0);
            stageB(cur ^ 1, k0);
            CPCOMMIT();
        }

        uint32_t a_st = cur ? AG_STAGEB : 0;
        int bbase = (cur * 2 + warp_n) * 16;      // row index into Bgen[.][72]
#pragma unroll
        for (int sub = 0; sub < 2; sub++) {
            uint32_t ah[2][4], al_[2][4];
#pragma unroll
            for (int mt = 0; mt < 2; mt++) {
                int r = m_base + mt * 16 + lrow;
                uint32_t unit = (uint32_t)((lu + sub * 2) ^ ((r >> 1) & 3));
                uint32_t off = a_st + (uint32_t)r * AG_ROWB + unit * 16;
                LDSM4(ah[mt][0], ah[mt][1], ah[mt][2], ah[mt][3], ah_b + off);
                LDSM4(al_[mt][0], al_[mt][1], al_[mt][2], al_[mt][3], al_b + off);
            }
#pragma unroll
            for (int ph = 0; ph < 2; ph++) {
                uint32_t bh[4][2];
#pragma unroll
                for (int nt = 0; nt < 4; nt++) {
                    int n = (ph * 4 + nt) * 8 + jq;
                    bh[nt][0] = *(const uint32_t*)&Bgen[(bbase + sub * 8 + jc) * 72 + n];
                    bh[nt][1] = *(const uint32_t*)&Bgen[(bbase + sub * 8 + jc + 4) * 72 + n];
                }
#pragma unroll
                for (int mt = 0; mt < 2; mt++)
#pragma unroll
                    for (int nt = 0; nt < 4; nt++) {
                        mma16(acc[mt][ph * 4 + nt], ah[mt], bh[nt]);
                        mma16(acc[mt][ph * 4 + nt], al_[mt], bh[nt]);
                    }
            }
        }
    }

    // ---- fp16 feature store + fused el/er (warp-local: warp owns full head) --
    float elv[4] = {0.f, 0.f, 0.f, 0.f}, erv[4] = {0.f, 0.f, 0.f, 0.f};
#pragma unroll
    for (int mt = 0; mt < 2; mt++)
#pragma unroll
        for (int nt = 0; nt < 8; nt++) {
            int r = row0 + m_base + mt * 16 + jq;
            int c = colw + nt * 8 + 2 * jc;
            if (r < M)
                *(__half2*)&Ch[(size_t)r * N + c] =
                    __floats2half2_rn(acc[mt][nt][0], acc[mt][nt][1]);
            if (r + 8 < M)
                *(__half2*)&Ch[(size_t)(r + 8) * N + c] =
                    __floats2half2_rn(acc[mt][nt][2], acc[mt][nt][3]);
            float w0 = pal[c], w1 = pal[c + 1];
            float u0 = pare[c], u1 = pare[c + 1];
            elv[mt * 2]     += acc[mt][nt][0] * w0 + acc[mt][nt][1] * w1;
            elv[mt * 2 + 1] += acc[mt][nt][2] * w0 + acc[mt][nt][3] * w1;
            erv[mt * 2]     += acc[mt][nt][0] * u0 + acc[mt][nt][1] * u1;
            erv[mt * 2 + 1] += acc[mt][nt][2] * u0 + acc[mt][nt][3] * u1;
        }
#pragma unroll
    for (int o = 1; o <= 2; o <<= 1) {
#pragma unroll
        for (int i = 0; i < 4; i++) {
            elv[i] += __shfl_xor_sync(0xffffffffu, elv[i], o);
            erv[i] += __shfl_xor_sync(0xffffffffu, erv[i], o);
        }
    }
    if (jc == 0) {
#pragma unroll
        for (int i = 0; i < 4; i++) {
            int r = row0 + m_base + (i >> 1) * 16 + (i & 1) * 8 + jq;
            if (r < M) {
                g_el[r * 4 + head] = elv[i];
                g_er[r * 4 + head] = erv[i];
            }
        }
    }
}

// ---------------- layer-2 GEMM (BK=16 path, verified) ------------------------
#define A_ROWB 48
#define A_STAGEB (128 * A_ROWB)
#define B2_ROWB 160
#define B2_STAGEB (8 * B2_ROWB)

__global__ __launch_bounds__(256, 2) void k_gemm16_tc(
    const __half* __restrict__ Axh, const __half* __restrict__ Axl,
    const __half2* __restrict__ Wph, const __half2* __restrict__ Wpl,
    float* __restrict__ feat2, float* __restrict__ res2,
    const float* __restrict__ al2, const float* __restrict__ ar2, int M) {
    const int K = 256;
    __shared__ __half2 Ah[2][128][12];
    __shared__ __half2 Al[2][128][12];
    __shared__ __half2 Bh[2][8][40];
    __shared__ __half2 Bl[2][8][40];

    int tid = threadIdx.x;
    int lane = tid & 31;
    int wid = tid >> 5;
    int m_base = wid * 16;
    int row0 = blockIdx.x * 128;

    float acc[4][4];
#pragma unroll
    for (int nt = 0; nt < 4; nt++)
#pragma unroll
        for (int i = 0; i < 4; i++) acc[nt][i] = 0.f;

    int ar = tid >> 1;
    int acq = (tid & 1);
    int gr = row0 + ar;
    int aok = (gr < M) ? 16 : 0;
    int grc = min(gr, M - 1);
    int t2 = tid & 63;
    int kp = t2 >> 3;
    int chk = t2 & 7;
    bool isB = tid < 128;
    bool isHi = tid < 64;

    uint32_t ah_b = (uint32_t)__cvta_generic_to_shared(&Ah[0][0][0]);
    uint32_t al_b = (uint32_t)__cvta_generic_to_shared(&Al[0][0][0]);
    uint32_t bh_b = (uint32_t)__cvta_generic_to_shared(&Bh[0][0][0]);
    uint32_t bl_b = (uint32_t)__cvta_generic_to_shared(&Bl[0][0][0]);
    uint32_t a_dst = ar * A_ROWB + acq * 16;
    uint32_t b_dst = (isHi ? bh_b : bl_b) + kp * B2_ROWB + chk * 16;
    const __half2* Wsrc = isHi ? Wph : Wpl;

    uint32_t lm_off = (uint32_t)(m_base + (lane & 7) + ((lane >> 3) & 1) * 8) * A_ROWB
                      + (lane >> 4) * 16;

    int jq = lane >> 2;
    int jc = lane & 3;

    {
        const __half* sa = Axh + (size_t)grc * K + acq * 8;
        const __half* sl = Axl + (size_t)grc * K + acq * 8;
        CP16(ah_b + a_dst, sa, aok);
        CP16(al_b + a_dst, sl, aok);
        if (isB) CP16(b_dst, Wsrc + (size_t)kp * 32 + chk * 4, 16);
        CPCOMMIT();
    }

    const int NS = K / 16;
    for (int s = 0; s < NS; s++) {
        int cur = s & 1;
        CPWAIT0();
        __syncthreads();
        if (s + 1 < NS) {
            int k0 = (s + 1) * 16;
            uint32_t stoff = (cur ^ 1) ? A_STAGEB : 0;
            const __half* sa = Axh + (size_t)grc * K + k0 + acq * 8;
            const __half* sl = Axl + (size_t)grc * K + k0 + acq * 8;
            CP16(ah_b + stoff + a_dst, sa, aok);
            CP16(al_b + stoff + a_dst, sl, aok);
            uint32_t bst = (cur ^ 1) ? B2_STAGEB : 0;
            if (isB) CP16(b_dst + bst, Wsrc + ((size_t)(k0 >> 1) + kp) * 32 + chk * 4, 16);
            CPCOMMIT();
        }

        uint32_t ah[4], al_[4];
        uint32_t a_st = cur ? A_STAGEB : 0;
        LDSM4(ah[0], ah[1], ah[2], ah[3], ah_b + a_st + lm_off);
        LDSM4(al_[0], al_[1], al_[2], al_[3], al_b + a_st + lm_off);
        uint32_t bh[4][2], bl[4][2];
#pragma unroll
        for (int nt = 0; nt < 4; nt++) {
            int n = nt * 8 + jq;
            bh[nt][0] = *(const uint32_t*)&Bh[cur][jc][n];
            bh[nt][1] = *(const uint32_t*)&Bh[cur][jc + 4][n];
            bl[nt][0] = *(const uint32_t*)&Bl[cur][jc][n];
            bl[nt][1] = *(const uint32_t*)&Bl[cur][jc + 4][n];
        }
#pragma unroll
        for (int nt = 0; nt < 4; nt++) {
            mma16(acc[nt], ah, bh[nt]);
            mma16(acc[nt], al_, bh[nt]);
            mma16(acc[nt], ah, bl[nt]);
        }
    }

    int r0 = row0 + m_base + jq;
    int r1 = r0 + 8;
    float elv0 = 0.f, elv1 = 0.f, erv0 = 0.f, erv1 = 0.f;
#pragma unroll
    for (int nt = 0; nt < 4; nt++) {
        int c = nt * 8 + 2 * jc;
        if (nt < 2) {
            if (r0 < M) *(float2*)&feat2[(size_t)r0 * 16 + c] = make_float2(acc[nt][0], acc[nt][1]);
            if (r1 < M) *(float2*)&feat2[(size_t)r1 * 16 + c] = make_float2(acc[nt][2], acc[nt][3]);
            float w0 = al2[c], w1 = al2[c + 1];
            float u0 = ar2[c], u1 = ar2[c + 1];
            elv0 += acc[nt][0] * w0 + acc[nt][1] * w1;
            elv1 += acc[nt][2] * w0 + acc[nt][3] * w1;
            erv0 += acc[nt][0] * u0 + acc[nt][1] * u1;
            erv1 += acc[nt][2] * u0 + acc[nt][3] * u1;
        } else {
            int cc = c - 16;
            if (r0 < M) *(float2*)&res2[(size_t)r0 * 16 + cc] = make_float2(acc[nt][0], acc[nt][1]);
            if (r1 < M) *(float2*)&res2[(size_t)r1 * 16 + cc] = make_float2(acc[nt][2], acc[nt][3]);
        }
    }
#pragma unroll
    for (int o = 1; o <= 2; o <<= 1) {
        elv0 += __shfl_xor_sync(0xffffffffu, elv0, o);
        elv1 += __shfl_xor_sync(0xffffffffu, elv1, o);
        erv0 += __shfl_xor_sync(0xffffffffu, erv0, o);
        erv1 += __shfl_xor_sync(0xffffffffu, erv1, o);
    }
    if (jc == 0) {
        if (r0 < M) { g_el[r0] = elv0; g_er[r0] = erv0; }
        if (r1 < M) { g_el[r1] = elv1; g_er[r1] = erv1; }
    }
}

// ---------------- fused softmax-aggregate (R12-verified, unroll x2) ----------
__device__ __forceinline__ float mishf(float x) {
    float sp = fmaxf(x, 0.f) + log1pf(__expf(-fabsf(x)));
    return x * tanhf(sp);
}

__device__ __forceinline__ float lrelu(float e) { return (e > 0.f) ? e : 0.2f * e; }

template <int MODE>
__global__ __launch_bounds__(256) void k_agg4(
    const __half* __restrict__ feath, const float* __restrict__ resf,
    const __half* __restrict__ resh, const __half* __restrict__ resl,
    const float* __restrict__ bias,
    __half* __restrict__ outh, __half* __restrict__ outl) {
    __shared__ float4 sw[8][32];
    int node = (blockIdx.x * blockDim.x + threadIdx.x) >> 5;
    int lane = threadIdx.x & 31;
    int warp = (threadIdx.x >> 5);
    if (node >= NN) return;
    int start = g_rowptr[node], end = g_rowptr[node + 1];
    float4 er4 = *(const float4*)&g_er[node * 4];
    int h = lane >> 3;
    float acc[8] = {0.f, 0.f, 0.f, 0.f, 0.f, 0.f, 0.f, 0.f};
    float ss0 = 0.f, ss1 = 0.f, ss2 = 0.f, ss3 = 0.f;

    for (int base = start; base < end; base += 32) {
        int i = base + lane;
        int s = 0;
        float w0 = 0.f, w1 = 0.f, w2 = 0.f, w3 = 0.f;
        if (i < end) {
            s = g_csr_src[i];
            float4 el4 = *(const float4*)&g_el[s * 4];
            w0 = __expf(lrelu(el4.x + er4.x));
            w1 = __expf(lrelu(el4.y + er4.y));
            w2 = __expf(lrelu(el4.z + er4.z));
            w3 = __expf(lrelu(el4.w + er4.w));
            ss0 += w0; ss1 += w1; ss2 += w2; ss3 += w3;
        }
        __syncwarp();
        sw[warp][lane] = make_float4(w0, w1, w2, w3);
        __syncwarp();
        int cnt = min(32, end - base);
        const float* swp = (const float*)&sw[warp][0];
        int j = 0;
        for (; j + 1 < cnt; j += 2) {
            int sjA = __shfl_sync(0xffffffffu, s, j);
            int sjB = __shfl_sync(0xffffffffu, s, j + 1);
            uint4 vA = *(const uint4*)(feath + (size_t)sjA * 256 + lane * 8);
            uint4 vB = *(const uint4*)(feath + (size_t)sjB * 256 + lane * 8);
            float wA = swp[j * 4 + h];
            float wB = swp[(j + 1) * 4 + h];
            float2 f0 = __half22float2(*(__half2*)&vA.x);
            float2 f1 = __half22float2(*(__half2*)&vA.y);
            float2 f2 = __half22float2(*(__half2*)&vA.z);
            float2 f3 = __half22float2(*(__half2*)&vA.w);
            acc[0] += wA * f0.x; acc[1] += wA * f0.y;
            acc[2] += wA * f1.x; acc[3] += wA * f1.y;
            acc[4] += wA * f2.x; acc[5] += wA * f2.y;
            acc[6] += wA * f3.x; acc[7] += wA * f3.y;
            f0 = __half22float2(*(__half2*)&vB.x);
            f1 = __half22float2(*(__half2*)&vB.y);
            f2 = __half22float2(*(__half2*)&vB.z);
            f3 = __half22float2(*(__half2*)&vB.w);
            acc[0] += wB * f0.x; acc[1] += wB * f0.y;
            acc[2] += wB * f1.x; acc[3] += wB * f1.y;
            acc[4] += wB * f2.x; acc[5] += wB * f2.y;
            acc[6] += wB * f3.x; acc[7] += wB * f3.y;
        }
        if (j < cnt) {
            int sj = __shfl_sync(0xffffffffu, s, j);
            uint4 v = *(const uint4*)(feath + (size_t)sj * 256 + lane * 8);
            float w = swp[j * 4 + h];
            float2 f0 = __half22float2(*(__half2*)&v.x);
            float2 f1 = __half22float2(*(__half2*)&v.y);
            float2 f2 = __half22float2(*(__half2*)&v.z);
            float2 f3 = __half22float2(*(__half2*)&v.w);
            acc[0] += w * f0.x; acc[1] += w * f0.y;
            acc[2] += w * f1.x; acc[3] += w * f1.y;
            acc[4] += w * f2.x; acc[5] += w * f2.y;
            acc[6] += w * f3.x; acc[7] += w * f3.y;
        }
    }
#pragma unroll
    for (int o = 16; o; o >>= 1) {
        ss0 += __shfl_xor_sync(0xffffffffu, ss0, o);
        ss1 += __shfl_xor_sync(0xffffffffu, ss1, o);
        ss2 += __shfl_xor_sync(0xffffffffu, ss2, o);
        ss3 += __shfl_xor_sync(0xffffffffu, ss3, o);
    }
    bool has = (end > start);
    float inv;
    {
        float sssel = (h == 0) ? ss0 : (h == 1) ? ss1 : (h == 2) ? ss2 : ss3;
        inv = has ? 1.f / sssel : 0.f;
    }

    size_t off = (size_t)node * 256 + lane * 8;
    int bc = lane * 8;
    float o[8];
    if (MODE == 0) {
        float4 r0 = *(const float4*)&resf[off];
        float4 r1 = *(const float4*)&resf[off + 4];
        o[0] = acc[0] * inv + r0.x + bias[bc];
        o[1] = acc[1] * inv + r0.y + bias[bc + 1];
        o[2] = acc[2] * inv + r0.z + bias[bc + 2];
        o[3] = acc[3] * inv + r0.w + bias[bc + 3];
        o[4] = acc[4] * inv + r1.x + bias[bc + 4];
        o[5] = acc[5] * inv + r1.y + bias[bc + 5];
        o[6] = acc[6] * inv + r1.z + bias[bc + 6];
        o[7] = acc[7] * inv + r1.w + bias[bc + 7];
    } else {
        uint4 vh = *(const uint4*)(resh + off);
        uint4 vl = *(const uint4*)(resl + off);
        float2 rh[4], rl[4];
        rh[0] = __half22float2(*(__half2*)&vh.x); rl[0] = __half22float2(*(__half2*)&vl.x);
        rh[1] = __half22float2(*(__half2*)&vh.y); rl[1] = __half22float2(*(__half2*)&vl.y);
        rh[2] = __half22float2(*(__half2*)&vh.z); rl[2] = __half22float2(*(__half2*)&vl.z);
        rh[3] = __half22float2(*(__half2*)&vh.w); rl[3] = __half22float2(*(__half2*)&vl.w);
#pragma unroll
        for (int q = 0; q < 4; q++) {
            o[2 * q]     = acc[2 * q] * inv + rh[q].x + rl[q].x + bias[bc + 2 * q];
            o[2 * q + 1] = acc[2 * q + 1] * inv + rh[q].y + rl[q].y + bias[bc + 2 * q + 1];
        }
    }
#pragma unroll
    for (int q = 0; q < 8; q++) o[q] = mishf(o[q]);
    uint4 vh, vl;
    __half2 hh, ll;
    split2(o[0], o[1], hh, ll); vh.x = *(uint32_t*)&hh; vl.x = *(uint32_t*)&ll;
    split2(o[2], o[3], hh, ll); vh.y = *(uint32_t*)&hh; vl.y = *(uint32_t*)&ll;
    split2(o[4], o[5], hh, ll); vh.z = *(uint32_t*)&hh; vl.z = *(uint32_t*)&ll;
    split2(o[6], o[7], hh, ll); vh.w = *(uint32_t*)&hh; vl.w = *(uint32_t*)&ll;
    *(uint4*)(outh + off) = vh;
    *(uint4*)(outl + off) = vl;
}

// ---------------- softmax-aggregate layer2 (R12-verified half-warp) ----------
__global__ __launch_bounds__(256) void k_agg2(
    const float* __restrict__ feat, const float* __restrict__ res,
    const float* __restrict__ bias, float* __restrict__ out) {
    int node = (blockIdx.x * blockDim.x + threadIdx.x) >> 5;
    int lane = threadIdx.x & 31;
    if (node >= NN) return;
    int start = g_rowptr[node], end = g_rowptr[node + 1];
    float er_n = g_er[node];
    int half = lane >> 4;
    int sub = lane & 15;

    float acc = 0.f, ss = 0.f;
    for (int base = start; base < end; base += 32) {
        int i = base + lane;
        int s = 0;
        float w = 0.f;
        if (i < end) {
            s = g_csr_src[i];
            w = __expf(lrelu(g_el[s] + er_n));
            ss += w;
        }
        int cnt = min(32, end - base);
        int j = 0;
        for (; j + 1 < cnt; j += 2) {
            int   sj = __shfl_sync(0xffffffffu, s, j + half);
            float bw = __shfl_sync(0xffffffffu, w, j + half);
            acc += bw * feat[(size_t)sj * 16 + sub];
        }
        if (j < cnt) {
            int   sj = __shfl_sync(0xffffffffu, s, j);
            float bw = __shfl_sync(0xffffffffu, w, j);
            if (half == 0) acc += bw * feat[(size_t)sj * 16 + sub];
        }
    }
#pragma unroll
    for (int o = 16; o; o >>= 1) ss += __shfl_xor_sync(0xffffffffu, ss, o);
    acc += __shfl_xor_sync(0xffffffffu, acc, 16);
    float inv = (end > start) ? 1.f / ss : 0.f;
    if (lane < 16)
        out[(size_t)node * 16 + lane] = acc * inv + res[(size_t)node * 16 + lane] + bias[lane];
}

// ---------------- launch -----------------------------------------------------
extern "C" void kernel_launch(void* const* d_in, const int* in_sizes, int n_in,
                              void* d_out, int out_size) {
    const float* x    = (const float*)d_in[0];
    const int*   src  = (const int*)d_in[1];
    const int*   dst  = (const int*)d_in[2];
    const float* W0   = (const float*)d_in[3];
    const float* al0  = (const float*)d_in[4];
    const float* ar0  = (const float*)d_in[5];
    const float* b0   = (const float*)d_in[6];
    const float* W1   = (const float*)d_in[7];
    const float* al1  = (const float*)d_in[8];
    const float* ar1  = (const float*)d_in[9];
    const float* b1   = (const float*)d_in[10];
    const float* W2   = (const float*)d_in[11];
    const float* al2  = (const float*)d_in[12];
    const float* ar2  = (const float*)d_in[13];
    const float* b2   = (const float*)d_in[14];
    const float* rW2  = (const float*)d_in[15];
    float* out = (float*)d_out;

    __half *feath, *xh, *xl, *h1h, *h1l;
    float *feat2, *res2;
    __half2 *w0h, *w1h, *w2h, *w2l;
    void* degp;
    cudaGetSymbolAddress((void**)&feath, g_feat_h);
    cudaGetSymbolAddress((void**)&xh, g_xh);
    cudaGetSymbolAddress((void**)&xl, g_xl);
    cudaGetSymbolAddress((void**)&h1h, g_h1h);
    cudaGetSymbolAddress((void**)&h1l, g_h1l);
    cudaGetSymbolAddress((void**)&feat2, g_feat2);
    cudaGetSymbolAddress((void**)&res2, g_res2);
    cudaGetSymbolAddress((void**)&w0h, g_w0h);
    cudaGetSymbolAddress((void**)&w1h, g_w1h);
    cudaGetSymbolAddress((void**)&w2h, g_w2h);
    cudaGetSymbolAddress((void**)&w2l, g_w2l);
    cudaGetSymbolAddress(&degp, g_deg);

    cudaFuncSetAttribute(k_gemm_tc, cudaFuncAttributeMaxDynamicSharedMemorySize, GEMM_SMEM);

    // fork a side stream for the CSR build
    cudaStream_t s2 = 0;
    cudaEvent_t evF = 0, evJ = 0;
    bool forked = (cudaStreamCreateWithFlags(&s2, cudaStreamNonBlocking) == cudaSuccess) &&
                  (cudaEventCreateWithFlags(&evF, cudaEventDisableTiming) == cudaSuccess) &&
                  (cudaEventCreateWithFlags(&evJ, cudaEventDisableTiming) == cudaSuccess);
    cudaStream_t sc = forked ? s2 : 0;

    if (forked) {
        cudaEventRecord(evF, 0);
        cudaStreamWaitEvent(s2, evF, 0);
    }
    cudaMemsetAsync(degp, 0, NN * sizeof(int), sc);
    k_hist<<<(NE + 255) / 256, 256, 0, sc>>>(dst);
    k_scan<<<1, 1024, 0, sc>>>();
    k_scatter<<<(NE + 255) / 256, 256, 0, sc>>>(src, dst);
    if (forked) cudaEventRecord(evJ, s2);

    // main stream: presplit + layer0 GEMM
    k_presplitW<<<(2 * 128 * 256 + 255) / 256, 256>>>(W0, W1, w0h, w1h);
    k_presplitW2<<<(128 * 32 + 255) / 256, 256>>>(W2, rW2, w2h, w2l);
    k_presplit<<<(NN * 64 + 255) / 256, 256>>>((const float4*)x, (uint2*)xh, (uint2*)xl, NN * 64);

    dim3 gtc(2, (NN + 127) / 128);
    int aggBlocks = (NN * 32 + 255) / 256;

    k_gemm_tc<<<gtc, 256, GEMM_SMEM>>>(xh, xl, w0h, feath, al0, ar0, NN);

    if (forked) cudaStreamWaitEvent(0, evJ, 0);

    k_agg4<0><<<aggBlocks, 256>>>(feath, x, nullptr, nullptr, b0, h1h, h1l);

    k_gemm_tc<<<gtc, 256, GEMM_SMEM>>>(h1h, h1l, w1h, feath, al1, ar1, NN);
    k_agg4<1><<<aggBlocks, 256>>>(feath, nullptr, h1h, h1l, b1, xh, xl);

    k_gemm16_tc<<<(NN + 127) / 128, 256>>>(xh, xl, w2h, w2l, feat2, res2, al2, ar2, NN);
    k_agg2<<<aggBlocks, 256>>>(feat2, res2, b2, out);
}